// round 11
// baseline (speedup 1.0000x reference)
#include <cuda_runtime.h>
#include <cuda_fp16.h>
#include <stdint.h>
#include <math.h>

#define NN 50000
#define NN2 50048          // padded to multiple of 64 for gemm2 tiles
#define FE 800000
#define ET (FE + NN)
#define NPART 196          // ceil(NN/256)
#define CH1 256
#define CH2 256

// ---------------- scratch ----------------------------------------------------
__device__ __half2 g_h1h[NN * 128];    // layer1 features fp16 (gather-only)
__device__ __half2 g_o1h[NN2 * 128];   // elu(layer1 out) fp16 (gemm2 A)
__device__ float   g_as1[NN * 4];
__device__ float   g_ad1[NN * 4];
__device__ __half  g_W2h[64 * 256];    // W2 fp16
__device__ __half2 g_h2h[NN2 * 32];    // layer2 pre-agg features fp16
__device__ float   g_as2[NN];
__device__ float   g_ad2[NN];
__device__ int     g_eid[ET];
__device__ int     g_cnt[NN];
__device__ int     g_off[NN + 1];
__device__ int     g_cur[NN];
__device__ int     g_part[NPART];
__device__ int     g_is64;
__device__ float   g_ws1s[64];
__device__ float   g_ws1d[64];
__device__ float   g_v2s[256];
__device__ float   g_v2d[256];

__device__ __forceinline__ float lrelu(float v) { return v > 0.f ? v : 0.2f * v; }
__device__ __forceinline__ float elu(float v)   { return v > 0.f ? v : expm1f(v); }
__device__ __forceinline__ uint32_t su32(const void* p) {
    return (uint32_t)__cvta_generic_to_shared(p);
}
#define NEG_INF __int_as_float(0xff800000)

// ---------------- setup: zero counters + dtype detect + weight folds ------------
__global__ void k_setup(const int* __restrict__ ei32,
                        const float* __restrict__ W1,
                        const float* __restrict__ as1, const float* __restrict__ ad1,
                        const float* __restrict__ W2,
                        const float* __restrict__ as2, const float* __restrict__ ad2) {
    int t = threadIdx.x;
    int i = blockIdx.x * blockDim.x + t;
    if (i < NN) g_cnt[i] = 0;
    if (blockIdx.x == 0) {
        int nz = 0;
        for (int k = t; k < 1024; k += 256) nz |= ei32[2 * k + 1];
        int any = __syncthreads_or(nz);
        if (t == 0) g_is64 = (any == 0);
    } else if (blockIdx.x == 1) {
        if (t < 64) {
            int h = t >> 4, ii = t & 15;
            float s = 0.f, d = 0.f;
            for (int c = 0; c < 64; c++) {
                float w = W1[(h * 64 + c) * 16 + ii];
                s += as1[h * 64 + c] * w;
                d += ad1[h * 64 + c] * w;
            }
            g_ws1s[t] = s; g_ws1d[t] = d;
        }
        {
            float s = 0.f, d = 0.f;
            for (int o = 0; o < 64; o++) {
                float w = W2[o * 256 + t];
                s += as2[o] * w;
                d += ad2[o] * w;
            }
            g_v2s[t] = s; g_v2d[t] = d;
        }
        for (int j = 0; j < 64; j++) {
            int idx = j * 256 + t;
            g_W2h[idx] = __float2half(W2[idx]);
        }
    }
}

// ---------------- edge in-degree count (stream B) ---------------------------------
__global__ void k_count(const int* __restrict__ ei32) {
    int i = blockIdx.x * blockDim.x + threadIdx.x;
    if (i >= ET) return;
    int d;
    if (i < FE) d = g_is64 ? ei32[2 * (FE + i)] : ei32[FE + i];
    else        d = i - FE;
    atomicAdd(&g_cnt[d], 1);
}

// ---------------- layer 1 GEMM + fused logits (stream A) --------------------------
__global__ void k_gemm1(const float* __restrict__ x, const float* __restrict__ W1) {
    __shared__ float xs[128];
    int t = threadIdx.x, b = blockIdx.x;
    if (t < 128) xs[t] = x[b * 128 + t];
    __syncthreads();
    if (t < 64) {   // logits: 8 nodes x 4 heads x {src,dst}
        int j = t >> 3, h = (t >> 1) & 3, sd = t & 1;
        const float* wv = (sd ? g_ws1d : g_ws1s) + h * 16;
        const float* xv = xs + j * 16;
        float a = 0.f;
#pragma unroll
        for (int i = 0; i < 16; i++) a += xv[i] * wv[i];
        int n = b * 8 + j;
        if (sd) g_ad1[n * 4 + h] = a; else g_as1[n * 4 + h] = a;
    }
    const float4* W4 = reinterpret_cast<const float4*>(W1) + t * 4;
    float4 w0 = W4[0], w1 = W4[1], w2 = W4[2], w3 = W4[3];
#pragma unroll
    for (int j = 0; j < 8; j++) {
        const float* xv = xs + j * 16;
        float acc = xv[0] * w0.x + xv[1] * w0.y + xv[2] * w0.z + xv[3] * w0.w
                  + xv[4] * w1.x + xv[5] * w1.y + xv[6] * w1.z + xv[7] * w1.w
                  + xv[8] * w2.x + xv[9] * w2.y + xv[10] * w2.z + xv[11] * w2.w
                  + xv[12] * w3.x + xv[13] * w3.y + xv[14] * w3.z + xv[15] * w3.w;
        float hi = __shfl_down_sync(0xffffffffu, acc, 1);
        if (!(t & 1)) g_h1h[(b * 8 + j) * 128 + (t >> 1)] = __floats2half2_rn(acc, hi);
    }
}

// ---------------- scan part: per-256-block sums -----------------------------------
__global__ void k_scan_part() {
    __shared__ int sm[256];
    int b = blockIdx.x, t = threadIdx.x, i = b * 256 + t;
    sm[t] = (i < NN) ? g_cnt[i] : 0;
    __syncthreads();
#pragma unroll
    for (int s = 128; s > 0; s >>= 1) { if (t < s) sm[t] += sm[t + s]; __syncthreads(); }
    if (t == 0) g_part[b] = sm[0];
}
// ---------------- scan finish: redundant partial-scan + local scan ----------------
__global__ void k_scan_fin2() {
    __shared__ int sp[256];
    __shared__ int sm[256];
    int b = blockIdx.x, t = threadIdx.x, i = b * 256 + t;
    sp[t] = (t < NPART) ? g_part[t] : 0;
    int v = (i < NN) ? g_cnt[i] : 0;
    sm[t] = v;
    __syncthreads();
#pragma unroll
    for (int s = 1; s < 256; s <<= 1) {
        int a = (t >= s) ? sp[t - s] : 0;
        int c = (t >= s) ? sm[t - s] : 0;
        __syncthreads();
        sp[t] += a; sm[t] += c;
        __syncthreads();
    }
    int base = (b > 0) ? sp[b - 1] : 0;      // exclusive prefix of parts
    if (i < NN) {
        int off = base + sm[t] - v;
        g_off[i] = off; g_cur[i] = off;
    }
    if (b == 0 && t == 0) g_off[NN] = ET;
}
__global__ void k_scatter(const int* __restrict__ ei32) {
    int i = blockIdx.x * blockDim.x + threadIdx.x;
    if (i >= ET) return;
    int s, d;
    if (i < FE) {
        if (g_is64) { s = ei32[2 * i]; d = ei32[2 * (FE + i)]; }
        else        { s = ei32[i];     d = ei32[FE + i]; }
    } else { s = i - FE; d = s; }
    int pos = atomicAdd(&g_cur[d], 1);
    g_eid[pos] = s;
}

// ---------------- layer 1 FUSED softmax + aggregate: warp-per-head, barrier-free --
__global__ void k_fagg1(const float* __restrict__ b1) {
    __shared__ float sw[4][CH1];
    __shared__ int   si[4][CH1];
    int d = blockIdx.x;
    int t = threadIdx.x;              // 128; warp h owns head h and channels [32h,32h+32)
    int lane = t & 31, h = t >> 5;
    int beg = g_off[d], end = g_off[d + 1];
    float ad = g_ad1[d * 4 + h];
    float* swh = sw[h];
    int* sih = si[h];
    float gm = NEG_INF, gs = 0.f, ax = 0.f, ay = 0.f;
    for (int cb = beg; cb < end; cb += CH1) {
        int cnt = min(end - cb, CH1);
        float m = NEG_INF;
        for (int e = lane; e < cnt; e += 32) {
            int s = g_eid[cb + e];
            sih[e] = s;
            float lg = lrelu(g_as1[s * 4 + h] + ad);
            swh[e] = lg;
            m = fmaxf(m, lg);
        }
#pragma unroll
        for (int o = 16; o > 0; o >>= 1) m = fmaxf(m, __shfl_xor_sync(0xffffffffu, m, o));
        float ss = 0.f;
        for (int e = lane; e < cnt; e += 32) {
            float w = __expf(swh[e] - m);
            swh[e] = w;
            ss += w;
        }
#pragma unroll
        for (int o = 16; o > 0; o >>= 1) ss += __shfl_xor_sync(0xffffffffu, ss, o);
        __syncwarp();
        // gather: unroll 8, four independent accumulator pairs
        float cax0 = 0.f, cay0 = 0.f, cax1 = 0.f, cay1 = 0.f;
        float cax2 = 0.f, cay2 = 0.f, cax3 = 0.f, cay3 = 0.f;
        int e = 0;
        for (; e + 8 <= cnt; e += 8) {
            int i0 = sih[e], i1 = sih[e + 1], i2 = sih[e + 2], i3 = sih[e + 3];
            int i4 = sih[e + 4], i5 = sih[e + 5], i6 = sih[e + 6], i7 = sih[e + 7];
            float w0 = swh[e], w1 = swh[e + 1], w2 = swh[e + 2], w3 = swh[e + 3];
            float w4 = swh[e + 4], w5 = swh[e + 5], w6 = swh[e + 6], w7 = swh[e + 7];
            float2 v0 = __half22float2(g_h1h[i0 * 128 + t]);
            float2 v1 = __half22float2(g_h1h[i1 * 128 + t]);
            float2 v2 = __half22float2(g_h1h[i2 * 128 + t]);
            float2 v3 = __half22float2(g_h1h[i3 * 128 + t]);
            float2 v4 = __half22float2(g_h1h[i4 * 128 + t]);
            float2 v5 = __half22float2(g_h1h[i5 * 128 + t]);
            float2 v6 = __half22float2(g_h1h[i6 * 128 + t]);
            float2 v7 = __half22float2(g_h1h[i7 * 128 + t]);
            cax0 += w0 * v0.x + w4 * v4.x;  cay0 += w0 * v0.y + w4 * v4.y;
            cax1 += w1 * v1.x + w5 * v5.x;  cay1 += w1 * v1.y + w5 * v5.y;
            cax2 += w2 * v2.x + w6 * v6.x;  cay2 += w2 * v2.y + w6 * v6.y;
            cax3 += w3 * v3.x + w7 * v7.x;  cay3 += w3 * v3.y + w7 * v7.y;
        }
        for (; e < cnt; e++) {
            float w = swh[e];
            float2 v = __half22float2(g_h1h[sih[e] * 128 + t]);
            cax0 += w * v.x; cay0 += w * v.y;
        }
        float cax = (cax0 + cax1) + (cax2 + cax3);
        float cay = (cay0 + cay1) + (cay2 + cay3);
        float nm = fmaxf(gm, m);
        float f = __expf(gm - nm), c = __expf(m - nm);
        gs = gs * f + ss * c;
        ax = ax * f + cax * c;
        ay = ay * f + cay * c;
        gm = nm;
        __syncwarp();
    }
    float inv = 1.f / (gs + 1e-16f);
    float2 bb = reinterpret_cast<const float2*>(b1)[t];
    float ox = elu(ax * inv + bb.x);
    float oy = elu(ay * inv + bb.y);
    g_o1h[d * 128 + t] = __floats2half2_rn(ox, oy);
}

// ---------------- layer 2 GEMM (tensor cores) + fused alpha2 epilogue -------------
#define MMA16816(C, A0, A1, A2, A3, B0, B1)                                   \
    asm volatile("mma.sync.aligned.m16n8k16.row.col.f32.f16.f16.f32 "          \
        "{%0,%1,%2,%3}, {%4,%5,%6,%7}, {%8,%9}, {%0,%1,%2,%3};"                \
        : "+f"(C[0]), "+f"(C[1]), "+f"(C[2]), "+f"(C[3])                       \
        : "r"(A0), "r"(A1), "r"(A2), "r"(A3), "r"(B0), "r"(B1))

__global__ void k_gemm2() {
    __shared__ __align__(16) __half sA[64 * 256];
    __shared__ __align__(16) __half sW[64 * 256];
    __shared__ float svs[256], svd[256];
    int t = threadIdx.x;               // 128
    int base = blockIdx.x * 64;
    const uint4* gA = reinterpret_cast<const uint4*>(g_o1h) + base * 32;
    const uint4* gW = reinterpret_cast<const uint4*>(g_W2h);
    svs[t] = g_v2s[t]; svs[t + 128] = g_v2s[t + 128];
    svd[t] = g_v2d[t]; svd[t + 128] = g_v2d[t + 128];
#pragma unroll
    for (int j = 0; j < 16; j++) {
        int i = j * 128 + t;
        int r = i >> 5, c = i & 31;
        int sc = c ^ (r & 7);
        *reinterpret_cast<uint4*>(&sA[r * 256 + sc * 8]) = gA[i];
        *reinterpret_cast<uint4*>(&sW[r * 256 + sc * 8]) = gW[i];
    }
    __syncthreads();
    int lane = t & 31, warp = t >> 5;
    int m0 = warp * 16;
    float acc[8][4];
#pragma unroll
    for (int i = 0; i < 8; i++)
#pragma unroll
        for (int j = 0; j < 4; j++) acc[i][j] = 0.f;

    int arow = m0 + (lane & 7) + ((lane >> 3) & 1) * 8;
    int akc  = (lane >> 4);
    int brin = ((lane >> 4) & 1) * 8 + (lane & 7);
    int bkc  = (lane >> 3) & 1;
#pragma unroll
    for (int kt = 0; kt < 16; kt++) {
        int ac = kt * 2 + akc;
        uint32_t aaddr = su32(&sA[arow * 256 + ((ac ^ (arow & 7)) << 3)]);
        uint32_t a0, a1, a2, a3;
        asm volatile("ldmatrix.sync.aligned.m8n8.x4.shared.b16 {%0,%1,%2,%3}, [%4];"
            : "=r"(a0), "=r"(a1), "=r"(a2), "=r"(a3) : "r"(aaddr));
#pragma unroll
        for (int og = 0; og < 4; og++) {
            int brow = og * 16 + brin;
            int bc = kt * 2 + bkc;
            uint32_t baddr = su32(&sW[brow * 256 + ((bc ^ (brow & 7)) << 3)]);
            uint32_t b0, b1, b2, b3;
            // W2 is [o][k] row-major = K x N col-major: plain (no .trans) B fragment
            asm volatile("ldmatrix.sync.aligned.m8n8.x4.shared.b16 {%0,%1,%2,%3}, [%4];"
                : "=r"(b0), "=r"(b1), "=r"(b2), "=r"(b3) : "r"(baddr));
            MMA16816(acc[og * 2],     a0, a1, a2, a3, b0, b1);
            MMA16816(acc[og * 2 + 1], a0, a1, a2, a3, b2, b3);
        }
    }
    int r0 = base + m0 + (lane >> 2);
    int cq = lane & 3;
#pragma unroll
    for (int ot = 0; ot < 8; ot++) {
        g_h2h[r0 * 32 + ot * 4 + cq]       = __floats2half2_rn(acc[ot][0], acc[ot][1]);
        g_h2h[(r0 + 8) * 32 + ot * 4 + cq] = __floats2half2_rn(acc[ot][2], acc[ot][3]);
    }
    // ---- alpha2 epilogue: 2 threads per node over the sA tile ----
    {
        int n = t >> 1, half = t & 1;
        const __half2* sa2 = reinterpret_cast<const __half2*>(sA);
        float a = 0.f, b = 0.f;
        int kk0 = half * 64;
#pragma unroll 8
        for (int kk = kk0; kk < kk0 + 64; kk++) {
            int c = kk >> 2, w2 = kk & 3;
            float2 v = __half22float2(sa2[n * 128 + ((c ^ (n & 7)) << 2) + w2]);
            a += v.x * svs[2 * kk] + v.y * svs[2 * kk + 1];
            b += v.x * svd[2 * kk] + v.y * svd[2 * kk + 1];
        }
        a += __shfl_xor_sync(0xffffffffu, a, 1);
        b += __shfl_xor_sync(0xffffffffu, b, 1);
        if (half == 0 && base + n < NN) { g_as2[base + n] = a; g_ad2[base + n] = b; }
    }
}

// ---------------- layer 2 FUSED softmax + aggregate + FINAL projection -------------
__global__ void k_fagg2(const float* __restrict__ b2,
                        const float* __restrict__ fw, const float* __restrict__ fb,
                        float* __restrict__ out) {
    __shared__ float sw[8][CH2];
    __shared__ int   si[8][CH2];
    int wid = threadIdx.x >> 5, lane = threadIdx.x & 31;
    int d = blockIdx.x * 8 + wid;
    int beg = g_off[d], end = g_off[d + 1];
    float ad = g_ad2[d];
    float gmv = NEG_INF, gsv = 0.f, ax = 0.f, ay = 0.f;
    for (int cb = beg; cb < end; cb += CH2) {
        int cnt = min(end - cb, CH2);
        float m = NEG_INF;
        for (int e = lane; e < cnt; e += 32) {
            int s = g_eid[cb + e];
            si[wid][e] = s;
            float lg = lrelu(g_as2[s] + ad);
            sw[wid][e] = lg;
            m = fmaxf(m, lg);
        }
#pragma unroll
        for (int o = 16; o > 0; o >>= 1) m = fmaxf(m, __shfl_xor_sync(0xffffffffu, m, o));
        float ssum = 0.f;
        for (int e = lane; e < cnt; e += 32) {
            float w = __expf(sw[wid][e] - m);
            sw[wid][e] = w;
            ssum += w;
        }
#pragma unroll
        for (int o = 16; o > 0; o >>= 1) ssum += __shfl_xor_sync(0xffffffffu, ssum, o);
        __syncwarp();
        float cax0 = 0.f, cay0 = 0.f, cax1 = 0.f, cay1 = 0.f;
        float cax2 = 0.f, cay2 = 0.f, cax3 = 0.f, cay3 = 0.f;
        const float* swh = sw[wid];
        const int* sih = si[wid];
        int e = 0;
        for (; e + 8 <= cnt; e += 8) {
            int i0 = sih[e], i1 = sih[e + 1], i2 = sih[e + 2], i3 = sih[e + 3];
            int i4 = sih[e + 4], i5 = sih[e + 5], i6 = sih[e + 6], i7 = sih[e + 7];
            float w0 = swh[e], w1 = swh[e + 1], w2 = swh[e + 2], w3 = swh[e + 3];
            float w4 = swh[e + 4], w5 = swh[e + 5], w6 = swh[e + 6], w7 = swh[e + 7];
            float2 v0 = __half22float2(g_h2h[i0 * 32 + lane]);
            float2 v1 = __half22float2(g_h2h[i1 * 32 + lane]);
            float2 v2 = __half22float2(g_h2h[i2 * 32 + lane]);
            float2 v3 = __half22float2(g_h2h[i3 * 32 + lane]);
            float2 v4 = __half22float2(g_h2h[i4 * 32 + lane]);
            float2 v5 = __half22float2(g_h2h[i5 * 32 + lane]);
            float2 v6 = __half22float2(g_h2h[i6 * 32 + lane]);
            float2 v7 = __half22float2(g_h2h[i7 * 32 + lane]);
            cax0 += w0 * v0.x + w4 * v4.x;  cay0 += w0 * v0.y + w4 * v4.y;
            cax1 += w1 * v1.x + w5 * v5.x;  cay1 += w1 * v1.y + w5 * v5.y;
            cax2 += w2 * v2.x + w6 * v6.x;  cay2 += w2 * v2.y + w6 * v6.y;
            cax3 += w3 * v3.x + w7 * v7.x;  cay3 += w3 * v3.y + w7 * v7.y;
        }
        for (; e < cnt; e++) {
            float w = swh[e];
            float2 v = __half22float2(g_h2h[sih[e] * 32 + lane]);
            cax0 += w * v.x; cay0 += w * v.y;
        }
        float cax = (cax0 + cax1) + (cax2 + cax3);
        float cay = (cay0 + cay1) + (cay2 + cay3);
        float nm = fmaxf(gmv, m);
        float f = __expf(gmv - nm), c = __expf(m - nm);
        gsv = gsv * f + ssum * c;
        ax = ax * f + cax * c;
        ay = ay * f + cay * c;
        gmv = nm;
        __syncwarp();
    }
    float inv = 1.f / (gsv + 1e-16f);
    float2 bb = reinterpret_cast<const float2*>(b2)[lane];
    float ox = elu(ax * inv + bb.x);
    float oy = elu(ay * inv + bb.y);
    // fused final projection: out[d] = sum_c o2[c]*fw[c] + fb
    float2 fwv = reinterpret_cast<const float2*>(fw)[lane];
    float v = ox * fwv.x + oy * fwv.y;
#pragma unroll
    for (int o = 16; o > 0; o >>= 1) v += __shfl_xor_sync(0xffffffffu, v, o);
    if (lane == 0) out[d] = v + fb[0];
}

// ---------------- launch --------------------------------------------------------------
extern "C" void kernel_launch(void* const* d_in, const int* in_sizes, int n_in,
                              void* d_out, int out_size) {
    const float* x   = (const float*)d_in[0];
    const int*   ei  = (const int*)d_in[1];
    const float* W1  = (const float*)d_in[2];
    const float* as1 = (const float*)d_in[3];
    const float* ad1 = (const float*)d_in[4];
    const float* b1  = (const float*)d_in[5];
    const float* W2  = (const float*)d_in[6];
    const float* as2 = (const float*)d_in[7];
    const float* ad2 = (const float*)d_in[8];
    const float* b2  = (const float*)d_in[9];
    const float* fw  = (const float*)d_in[10];
    const float* fb  = (const float*)d_in[11];
    float*       out = (float*)d_out;

    // one-time infra init (host-side handles; happens on the uncaptured
    // correctness call, reused identically on every call thereafter)
    static cudaStream_t sB = nullptr;
    static cudaEvent_t evFork = nullptr, evJoin = nullptr;
    if (sB == nullptr) {
        cudaStreamCreateWithFlags(&sB, cudaStreamNonBlocking);
        cudaEventCreateWithFlags(&evFork, cudaEventDisableTiming);
        cudaEventCreateWithFlags(&evJoin, cudaEventDisableTiming);
    }

    k_setup<<<NPART, 256>>>(ei, W1, as1, ad1, W2, as2, ad2);
    // fork: CSR build on stream B, gemm1 on the main stream — independent work
    cudaEventRecord(evFork, 0);
    cudaStreamWaitEvent(sB, evFork, 0);
    k_count<<<(ET + 255) / 256, 256, 0, sB>>>(ei);
    k_scan_part<<<NPART, 256, 0, sB>>>();
    k_scan_fin2<<<NPART, 256, 0, sB>>>();
    k_scatter<<<(ET + 255) / 256, 256, 0, sB>>>(ei);
    cudaEventRecord(evJoin, sB);
    k_gemm1<<<NN / 8, 256>>>(x, W1);
    cudaStreamWaitEvent(0, evJoin, 0);
    // join: everything below needs both branches
    k_fagg1<<<NN, 128>>>(b1);
    k_gemm2<<<NN2 / 64, 128>>>();
    k_fagg2<<<NN / 8, 256>>>(b2, fw, fb, out);
}